// round 13
// baseline (speedup 1.0000x reference)
#include <cuda_runtime.h>
#include <cuda_fp16.h>
#include <cstdint>

#define BATCH 128
#define ITEMS 8000
#define CONC  128
#define EMB   32
#define TI    32
#define NBLK  (ITEMS / TI)    // 250

#define QWHS 136    // qw' row stride (halves)
#define W1HS 40     // w1h row stride (halves)
#define IEHS 40     // ieh row stride (halves)
#define EMHS 40     // embh row stride (halves)

// float-offset smem map
#define OFF_AH    0        // stuC A' fragment blocks: 16384 halves = 8192 f
#define OFF_QWH   8192     // qw' fp16: 32*136 halves = 2176 f
#define OFF_W1H   10368    // 128*40 halves = 2560 f
#define OFF_IEH   12928    // 32*40 halves  = 640 f
#define OFF_EMBH  13568    // 128*40 halves = 2560 f
#define OFF_PART  16128    // 16*32
#define OFF_PARTQ 16640    // 16*32
#define OFF_B1    17152    // 128
#define OFF_WP    17280    // 128
#define OFF_GQ    17408    // 128
#define OFF_ZC    17536    // 32
#define OFF_QA    17568    // 32
#define OFF_DISC  17600    // 32
#define OFF_GSU   17632    // 128
#define OFF_POLY  17760    // 8
#define OFF_IDX   17768    // 128 (int)
#define SMEM_FLOATS 17896
#define SMEM_BYTES  (SMEM_FLOATS * 4)   // 71584 B -> 2 CTAs/SM

__device__ __forceinline__ float sigmoidf(float x) {
    return __fdividef(1.0f, 1.0f + __expf(-x));
}
__device__ __forceinline__ float sigt(float x) {
    float t;
    asm("tanh.approx.f32 %0, %1;" : "=f"(t) : "f"(x * 0.5f));
    return fmaf(0.5f, t, 0.5f);
}
__device__ __forceinline__ void mma_f16(float* d, const uint4 a, const uint2 b) {
    asm("mma.sync.aligned.m16n8k16.row.col.f32.f16.f16.f32 "
        "{%0,%1,%2,%3}, {%4,%5,%6,%7}, {%8,%9}, {%0,%1,%2,%3};"
        : "+f"(d[0]), "+f"(d[1]), "+f"(d[2]), "+f"(d[3])
        : "r"(a.x), "r"(a.y), "r"(a.z), "r"(a.w), "r"(b.x), "r"(b.y));
}
__device__ __forceinline__ void cp16(float* dst_smem, const void* src) {
    unsigned d = (unsigned)__cvta_generic_to_shared(dst_smem);
    asm volatile("cp.async.ca.shared.global [%0], [%1], 16;\n" :: "r"(d), "l"(src));
}

// ---------------------------------------------------------------------------
// ONE kernel: 250 CTAs x 512 thr, 32 items each, 2 CTAs/SM.
//   prologue: params + fp16 conversions (w1, ie) + stu gather (emb2, gsu)
//   phase B : itemC GEMM on tensor cores + qw' + per-item partials
//   phase A : stuC GEMM on tensor cores -> A' fragment smem (D-frag == A-frag)
//   phase C : term1 = stuC @ qw'^T on tensor cores, fused epilogue
// ---------------------------------------------------------------------------
__global__ void __launch_bounds__(512, 2) main_kernel(
    const int*   __restrict__ stu_list,
    const float* __restrict__ stu_emb,
    const float* __restrict__ item_emb,
    const float* __restrict__ disc,
    const float* __restrict__ Q,
    const float* __restrict__ w1,
    const float* __restrict__ b1,
    const float* __restrict__ wp,
    const float* __restrict__ bp,
    const float* __restrict__ gw_stu,
    const float* __restrict__ gw_Q,
    const float* __restrict__ w2,
    const float* __restrict__ b2,
    float* __restrict__ out)
{
    extern __shared__ float sm[];
    __half* s_Ah   = (__half*)(sm + OFF_AH);
    __half* s_qwh  = (__half*)(sm + OFF_QWH);
    __half* s_w1h  = (__half*)(sm + OFF_W1H);
    __half* s_ieh  = (__half*)(sm + OFF_IEH);
    __half* s_embh = (__half*)(sm + OFF_EMBH);
    float* s_part  = sm + OFF_PART;
    float* s_partq = sm + OFF_PARTQ;
    float* s_b1    = sm + OFF_B1;
    float* s_wp    = sm + OFF_WP;
    float* s_gq    = sm + OFF_GQ;
    float* s_zc    = sm + OFF_ZC;
    float* s_qa    = sm + OFF_QA;
    float* s_disc  = sm + OFF_DISC;
    float* s_gsu   = sm + OFF_GSU;
    float* s_poly  = sm + OFF_POLY;
    int*   s_idx   = (int*)(sm + OFF_IDX);

    const int tid  = threadIdx.x;
    const int wid  = tid >> 5;
    const int lane = tid & 31;
    const int gid  = lane >> 2;
    const int tig  = lane & 3;
    const int i0   = blockIdx.x * TI;

    // ---- params via cp.async ----
    if (tid < 32)       cp16(s_b1 + tid * 4, b1 + tid * 4);
    else if (tid < 64)  cp16(s_wp + (tid - 32) * 4, wp + (tid - 32) * 4);
    else if (tid < 96)  cp16(s_gq + (tid - 64) * 4, gw_Q + (tid - 64) * 4);
    else if (tid < 104) cp16(s_disc + (tid - 96) * 4, disc + i0 + (tid - 96) * 4);
    asm volatile("cp.async.commit_group;\n" ::: "memory");

    // ---- student index + gsu gather ----
    if (tid >= 256 && tid < 384) {
        const int b = tid - 256;
        const int idx = stu_list[b] - 1;
        s_idx[b] = idx;
        s_gsu[b] = gw_stu[idx];
    }

    // ---- fp32 -> fp16 conversions into fragment-strided tiles ----
    for (int j = tid; j < 2048; j += 512) {                // w1
        const float2 v = ((const float2*)w1)[j];
        *(__half2*)(s_w1h + (j >> 4) * W1HS + 2 * (j & 15)) =
            __floats2half2_rn(v.x, v.y);
    }
    if (tid < 512) {                                       // ie (512 f2)
        const int j = tid;
        const float2 v = ((const float2*)(item_emb + (size_t)i0 * EMB))[j];
        *(__half2*)(s_ieh + (j >> 4) * IEHS + 2 * (j & 15)) =
            __floats2half2_rn(v.x, v.y);
    }

    const float bpv = bp[0];

    // ---- g2 degree-6 Newton interpolation setup (warp 0) ----
    if (wid == 0) {
        const float w2v = w2[0];
        const float b2v = b2[0];
        const float h = 1.0f / 6.0f;
        float fk = sigmoidf(fmaf(w2v, h * (float)(lane < 7 ? lane : 0), b2v));
        const float f0 = __shfl_sync(0xffffffffu, fk, 0);
        const float f1 = __shfl_sync(0xffffffffu, fk, 1);
        const float f2 = __shfl_sync(0xffffffffu, fk, 2);
        const float f3 = __shfl_sync(0xffffffffu, fk, 3);
        const float f4 = __shfl_sync(0xffffffffu, fk, 4);
        const float f5 = __shfl_sync(0xffffffffu, fk, 5);
        const float f6 = __shfl_sync(0xffffffffu, fk, 6);
        if (lane == 0) {
            const float d1 = f1 - f0;
            const float d2 = f2 - 2.0f * f1 + f0;
            const float d3 = f3 - 3.0f * f2 + 3.0f * f1 - f0;
            const float d4 = f4 - 4.0f * f3 + 6.0f * f2 - 4.0f * f1 + f0;
            const float d5 = f5 - 5.0f * f4 + 10.0f * f3 - 10.0f * f2
                             + 5.0f * f1 - f0;
            const float d6 = f6 - 6.0f * f5 + 15.0f * f4 - 20.0f * f3
                             + 15.0f * f2 - 6.0f * f1 + f0;
            s_poly[0] = f0;
            s_poly[1] = d1;
            s_poly[2] = d2 * 0.5f;
            s_poly[3] = d3 * (1.0f / 6.0f);
            s_poly[4] = d4 * (1.0f / 24.0f);
            s_poly[5] = d5 * (1.0f / 120.0f);
            s_poly[6] = d6 * (1.0f / 720.0f);
        }
    }

    asm volatile("cp.async.wait_group 0;\n" ::: "memory");
    __syncthreads();

    // ---- gathered student embeddings -> s_embh (fragment-strided fp16) ----
#pragma unroll
    for (int q = 0; q < 4; q++) {
        const int j = tid + 512 * q;       // 2048 float2 total
        const int r = j >> 4, c2 = j & 15;
        const float2 v = *(const float2*)(stu_emb + (size_t)s_idx[r] * EMB + 2 * c2);
        *(__half2*)(s_embh + r * EMHS + 2 * c2) = __floats2half2_rn(v.x, v.y);
    }

    // ---- phase B: itemC GEMM + qw' + per-item partials ----
    {
        const int c = 8 * wid + 2 * tig;

        float2 qv[4];
#pragma unroll
        for (int s = 0; s < 4; s++) {
            const int item = 8 * s + gid;
            qv[s] = *(const float2*)(Q + (size_t)(i0 + item) * CONC + c);
        }

        float acc[2][4];
#pragma unroll
        for (int mi = 0; mi < 2; mi++)
#pragma unroll
            for (int r = 0; r < 4; r++) acc[mi][r] = 0.0f;

#pragma unroll
        for (int kc = 0; kc < 2; kc++) {
            uint2 bb;
            bb.x = *(const uint32_t*)(s_w1h + (8 * wid + gid) * W1HS + 16 * kc + 2 * tig);
            bb.y = *(const uint32_t*)(s_w1h + (8 * wid + gid) * W1HS + 16 * kc + 2 * tig + 8);
#pragma unroll
            for (int mi = 0; mi < 2; mi++) {
                uint4 aa;
                aa.x = *(const uint32_t*)(s_ieh + (16 * mi + gid) * IEHS + 16 * kc + 2 * tig);
                aa.y = *(const uint32_t*)(s_ieh + (16 * mi + gid + 8) * IEHS + 16 * kc + 2 * tig);
                aa.z = *(const uint32_t*)(s_ieh + (16 * mi + gid) * IEHS + 16 * kc + 2 * tig + 8);
                aa.w = *(const uint32_t*)(s_ieh + (16 * mi + gid + 8) * IEHS + 16 * kc + 2 * tig + 8);
                mma_f16(acc[mi], aa, bb);
            }
        }

        const float b1c0 = s_b1[c],  b1c1 = s_b1[c + 1];
        const float wp0  = s_wp[c],  wp1  = s_wp[c + 1];
        const float gq0  = s_gq[c],  gq1  = s_gq[c + 1];
        const int   slot = 16 * (wid >> 1) + 4 * tig + 2 * (wid & 1);

        float pr[4], qa[4];
#pragma unroll
        for (int mi = 0; mi < 2; mi++)
#pragma unroll
            for (int h = 0; h < 2; h++) {
                const int s    = 2 * mi + h;
                const int item = 16 * mi + 8 * h + gid;
                const float ic0 = sigt(acc[mi][2 * h]     + b1c0);
                const float ic1 = sigt(acc[mi][2 * h + 1] + b1c1);
                const float q0 = (h == 0) ? ((mi == 0) ? qv[0].x : qv[2].x)
                                          : ((mi == 0) ? qv[1].x : qv[3].x);
                const float q1 = (h == 0) ? ((mi == 0) ? qv[0].y : qv[2].y)
                                          : ((mi == 0) ? qv[1].y : qv[3].y);
                const float qw0 = q0 * wp0;
                const float qw1 = q1 * wp1;
                *(__half2*)(s_qwh + item * QWHS + slot) = __floats2half2_rn(qw0, qw1);
                pr[s] = fmaf(qw0, ic0, qw1 * ic1);
                qa[s] = fmaf(q0, gq0, q1 * gq1);
            }
#pragma unroll
        for (int s = 0; s < 4; s++) {
            pr[s] += __shfl_down_sync(0xffffffffu, pr[s], 2, 4);
            pr[s] += __shfl_down_sync(0xffffffffu, pr[s], 1, 4);
            qa[s] += __shfl_down_sync(0xffffffffu, qa[s], 2, 4);
            qa[s] += __shfl_down_sync(0xffffffffu, qa[s], 1, 4);
        }
        if (tig == 0) {
#pragma unroll
            for (int mi = 0; mi < 2; mi++)
#pragma unroll
                for (int h = 0; h < 2; h++) {
                    const int item = 16 * mi + 8 * h + gid;
                    s_part [wid * 32 + item] = pr[2 * mi + h];
                    s_partq[wid * 32 + item] = qa[2 * mi + h];
                }
        }
    }
    __syncthreads();    // s_embh + partials + s_qwh ready

    // ---- phase A: stuC GEMM -> A' fragment smem ----
    // warp: stu rows [16*(wid&7), +16), conc cols [64*(wid>>3), +64)
    {
        const int wm2 = wid & 7;
        const int wn2 = wid >> 3;
#pragma unroll
        for (int cb = 0; cb < 4; cb++) {
            const int C0 = 64 * wn2 + 16 * cb;
            float a0[4] = {0, 0, 0, 0}, a1[4] = {0, 0, 0, 0};
#pragma unroll
            for (int kc = 0; kc < 2; kc++) {
                uint4 aa;
                aa.x = *(const uint32_t*)(s_embh + (16 * wm2 + gid) * EMHS + 16 * kc + 2 * tig);
                aa.y = *(const uint32_t*)(s_embh + (16 * wm2 + gid + 8) * EMHS + 16 * kc + 2 * tig);
                aa.z = *(const uint32_t*)(s_embh + (16 * wm2 + gid) * EMHS + 16 * kc + 2 * tig + 8);
                aa.w = *(const uint32_t*)(s_embh + (16 * wm2 + gid + 8) * EMHS + 16 * kc + 2 * tig + 8);
                uint2 b0, b1f;
                b0.x  = *(const uint32_t*)(s_w1h + (C0 + gid) * W1HS + 16 * kc + 2 * tig);
                b0.y  = *(const uint32_t*)(s_w1h + (C0 + gid) * W1HS + 16 * kc + 2 * tig + 8);
                b1f.x = *(const uint32_t*)(s_w1h + (C0 + 8 + gid) * W1HS + 16 * kc + 2 * tig);
                b1f.y = *(const uint32_t*)(s_w1h + (C0 + 8 + gid) * W1HS + 16 * kc + 2 * tig + 8);
                mma_f16(a0, aa, b0);
                mma_f16(a1, aa, b1f);
            }
            const float ba = s_b1[C0 + 2 * tig],     bb = s_b1[C0 + 2 * tig + 1];
            const float bc = s_b1[C0 + 8 + 2 * tig], bd = s_b1[C0 + 8 + 2 * tig + 1];
            const __half2 h0 = __floats2half2_rn(sigt(a0[0] + ba), sigt(a0[1] + bb));
            const __half2 h1 = __floats2half2_rn(sigt(a0[2] + ba), sigt(a0[3] + bb));
            const __half2 h2 = __floats2half2_rn(sigt(a1[0] + bc), sigt(a1[1] + bd));
            const __half2 h3 = __floats2half2_rn(sigt(a1[2] + bc), sigt(a1[3] + bd));
            uint4 v;
            v.x = *(const uint32_t*)&h0;
            v.y = *(const uint32_t*)&h1;
            v.z = *(const uint32_t*)&h2;
            v.w = *(const uint32_t*)&h3;
            *(uint4*)(s_Ah + (wm2 * 8 + (C0 >> 4)) * 256 + (gid * 4 + tig) * 8) = v;
        }
    }

    // cross-warp reduce of per-item partials (warp 0, concurrent w/ phase A)
    if (tid < 32) {
        float t2 = 0.0f, qa = 0.0f;
#pragma unroll
        for (int w = 0; w < 16; w++) {
            t2 += s_part [w * 32 + tid];
            qa += s_partq[w * 32 + tid];
        }
        s_zc[tid] = fmaf(-s_disc[tid], t2, bpv);
        s_qa[tid] = qa;
    }
    __syncthreads();

    // ---- phase C: term1 GEMM, warp tile 16(b) x 16(i) ----
    const int wm = wid >> 1;
    const int wn = wid & 1;

    float acc[2][4];
#pragma unroll
    for (int ni = 0; ni < 2; ni++)
#pragma unroll
        for (int r = 0; r < 4; r++) acc[ni][r] = 0.0f;

    const __half* pa  = s_Ah + wm * 2048 + (gid * 4 + tig) * 8;
    const __half* pb0 = s_qwh + (16 * wn + gid) * QWHS + 4 * tig;
#pragma unroll
    for (int kb = 0; kb < 8; kb++) {
        const uint4 a   = *(const uint4*)(pa + kb * 256);
        const uint2 b0  = *(const uint2*)(pb0 + kb * 16);
        const uint2 b1v = *(const uint2*)(pb0 + 8 * QWHS + kb * 16);
        mma_f16(acc[0], a, b0);
        mma_f16(acc[1], a, b1v);
    }

    // ---- fused epilogue ----
    const float F0 = s_poly[0], D1 = s_poly[1], D2 = s_poly[2],
                D3 = s_poly[3], D4 = s_poly[4], D5 = s_poly[5],
                D6 = s_poly[6];
#pragma unroll
    for (int h = 0; h < 2; h++) {
        const int row = 16 * wm + 8 * h + gid;
        const float gs = s_gsu[row];
        float* orow = out + (size_t)row * ITEMS + i0;
#pragma unroll
        for (int ni = 0; ni < 2; ni++) {
            const int col = 16 * wn + 8 * ni + 2 * tig;
            float res[2];
#pragma unroll
            for (int e = 0; e < 2; e++) {
                const int il = col + e;
                const float t1 = acc[ni][2 * h + e];
                const float z  = fmaf(s_disc[il], t1, s_zc[il]);
                const float P  = sigt(z);
                const float g1 = sigt(gs + s_qa[il]);
                const float v = 6.0f * g1;
                float tp = D6;
                tp = fmaf(v - 5.0f, tp, D5);
                tp = fmaf(v - 4.0f, tp, D4);
                tp = fmaf(v - 3.0f, tp, D3);
                tp = fmaf(v - 2.0f, tp, D2);
                tp = fmaf(v - 1.0f, tp, D1);
                const float g2 = fmaf(v, tp, F0);
                res[e] = fmaf(1.0f - g2, P, g2);
            }
            *(float2*)(orow + col) = make_float2(res[0], res[1]);
        }
    }
}

// ---------------------------------------------------------------------------
extern "C" void kernel_launch(void* const* d_in, const int* in_sizes, int n_in,
                              void* d_out, int out_size) {
    const int*   stu_list = (const int*)  d_in[0];
    const float* stu_emb  = (const float*)d_in[1];
    const float* item_emb = (const float*)d_in[2];
    const float* disc     = (const float*)d_in[3];
    const float* Q        = (const float*)d_in[4];
    const float* w1       = (const float*)d_in[5];
    const float* b1       = (const float*)d_in[6];
    const float* wp       = (const float*)d_in[7];
    const float* bp       = (const float*)d_in[8];
    const float* gw_stu   = (const float*)d_in[9];
    const float* gw_Q     = (const float*)d_in[10];
    const float* w2       = (const float*)d_in[11];
    const float* b2       = (const float*)d_in[12];
    float* out = (float*)d_out;

    cudaFuncSetAttribute(main_kernel, cudaFuncAttributeMaxDynamicSharedMemorySize,
                         SMEM_BYTES);
    main_kernel<<<NBLK, 512, SMEM_BYTES>>>(stu_list, stu_emb, item_emb, disc, Q,
                                           w1, b1, wp, bp, gw_stu, gw_Q, w2, b2,
                                           out);
}

// round 14
// speedup vs baseline: 1.0961x; 1.0961x over previous
#include <cuda_runtime.h>
#include <cuda_fp16.h>
#include <cstdint>

#define BATCH 128
#define ITEMS 8000
#define CONC  128
#define EMB   32
#define TI    32
#define NBLK  (ITEMS / TI)    // 250

#define QWHS 136    // qw' row stride (halves)
#define W1HS 40     // w1h row stride (halves)
#define IEHS 40     // ieh row stride (halves)

// float-offset smem map (no A' tile anymore)
#define OFF_QWH   0        // 32*136 halves = 2176 f
#define OFF_W1H   2176     // 128*40 halves = 2560 f
#define OFF_IEH   4736     // 32*40 halves  = 640 f
#define OFF_PART  5376     // 16*32
#define OFF_PARTQ 5888     // 16*32
#define OFF_B1    6400     // 128
#define OFF_WP    6528     // 128
#define OFF_GQ    6656     // 128
#define OFF_ZC    6784     // 32
#define OFF_QA    6816     // 32
#define OFF_DISC  6848     // 32
#define OFF_POLY  6880     // 8
#define SMEM_FLOATS 6888
#define SMEM_BYTES  (SMEM_FLOATS * 4)   // 27552 B

__device__ __half g_stuC[BATCH * CONC];  // fp16, fragment-block order
__device__ float  g_gsu[BATCH];

__device__ __forceinline__ float sigmoidf(float x) {
    return __fdividef(1.0f, 1.0f + __expf(-x));
}
__device__ __forceinline__ float sigt(float x) {
    float t;
    asm("tanh.approx.f32 %0, %1;" : "=f"(t) : "f"(x * 0.5f));
    return fmaf(0.5f, t, 0.5f);
}
__device__ __forceinline__ void mma_f16(float* d, const uint4 a, const uint2 b) {
    asm("mma.sync.aligned.m16n8k16.row.col.f32.f16.f16.f32 "
        "{%0,%1,%2,%3}, {%4,%5,%6,%7}, {%8,%9}, {%0,%1,%2,%3};"
        : "+f"(d[0]), "+f"(d[1]), "+f"(d[2]), "+f"(d[3])
        : "r"(a.x), "r"(a.y), "r"(a.z), "r"(a.w), "r"(b.x), "r"(b.y));
}
__device__ __forceinline__ void cp16(float* dst_smem, const void* src) {
    unsigned d = (unsigned)__cvta_generic_to_shared(dst_smem);
    asm volatile("cp.async.ca.shared.global [%0], [%1], 16;\n" :: "r"(d), "l"(src));
}
// fragment-block half index for stuC[b][c]  (m16n8k16 A fragment order)
__device__ __forceinline__ int fragIdxH(int b, int c) {
    const int blk  = (b >> 4) * 8 + (c >> 4);
    const int rr   = b & 7;
    const int hi8  = (b >> 3) & 1;
    const int c15  = c & 15;
    const int tigc = (c15 >> 1) & 3;
    const int khi  = (c15 >> 3) & 1;
    const int lo   = c15 & 1;
    return blk * 256 + (rr * 4 + tigc) * 8 + (khi * 2 + hi8) * 2 + lo;
}

// ---------------------------------------------------------------------------
// Kernel 1: 16 CTAs x 512 thr; 8 students each. Fragment-order fp16 output.
// ---------------------------------------------------------------------------
__global__ void __launch_bounds__(512) stu_kernel(
    const int*   __restrict__ stu_list,
    const float* __restrict__ stu_emb,
    const float* __restrict__ w1,
    const float* __restrict__ b1,
    const float* __restrict__ gw_stu)
{
    __shared__ float s_w1[CONC * 33];
    __shared__ float s_emb[8 * EMB];
    __shared__ int   s_sidx[8];

    asm volatile("griddepcontrol.launch_dependents;");

    const int t  = threadIdx.x;
    const int b0 = blockIdx.x * 8;

    if (t < 8) {
        const int idx = stu_list[b0 + t] - 1;
        s_sidx[t] = idx;
        g_gsu[b0 + t] = gw_stu[idx];
    }
    for (int j = t; j < CONC * EMB; j += 512)
        s_w1[(j >> 5) * 33 + (j & 31)] = w1[j];
    __syncthreads();
    if (t < 8 * EMB)
        s_emb[t] = stu_emb[(size_t)s_sidx[t >> 5] * EMB + (t & 31)];
    __syncthreads();

    const int c  = t & 127;
    const int sl = t >> 7;
    const float b1c = b1[c];
#pragma unroll
    for (int r = 0; r < 2; r++) {
        const int s = sl + 4 * r;
        float z = b1c;
#pragma unroll
        for (int k = 0; k < EMB; k++)
            z = fmaf(s_emb[s * EMB + k], s_w1[c * 33 + k], z);
        g_stuC[fragIdxH(b0 + s, c)] = __float2half(sigmoidf(z));
    }
}

// ---------------------------------------------------------------------------
// Kernel 2 (PDL dependent): 250 CTAs x 512 thr, 32 items each, 2 CTAs/SM.
// Phase C reads A fragments DIRECTLY from gmem (fragment-order, L2-hot).
// ---------------------------------------------------------------------------
__global__ void __launch_bounds__(512, 2) main_kernel(
    const float* __restrict__ item_emb,
    const float* __restrict__ disc,
    const float* __restrict__ Q,
    const float* __restrict__ w1,
    const float* __restrict__ b1,
    const float* __restrict__ wp,
    const float* __restrict__ bp,
    const float* __restrict__ gw_Q,
    const float* __restrict__ w2,
    const float* __restrict__ b2,
    float* __restrict__ out)
{
    extern __shared__ float sm[];
    __half* s_qwh  = (__half*)(sm + OFF_QWH);
    __half* s_w1h  = (__half*)(sm + OFF_W1H);
    __half* s_ieh  = (__half*)(sm + OFF_IEH);
    float* s_part  = sm + OFF_PART;
    float* s_partq = sm + OFF_PARTQ;
    float* s_b1    = sm + OFF_B1;
    float* s_wp    = sm + OFF_WP;
    float* s_gq    = sm + OFF_GQ;
    float* s_zc    = sm + OFF_ZC;
    float* s_qa    = sm + OFF_QA;
    float* s_disc  = sm + OFF_DISC;
    float* s_poly  = sm + OFF_POLY;

    const int tid  = threadIdx.x;
    const int wid  = tid >> 5;
    const int lane = tid & 31;
    const int gid  = lane >> 2;
    const int tig  = lane & 3;
    const int i0   = blockIdx.x * TI;

    // ---- params via cp.async ----
    if (tid < 32)       cp16(s_b1 + tid * 4, b1 + tid * 4);
    else if (tid < 64)  cp16(s_wp + (tid - 32) * 4, wp + (tid - 32) * 4);
    else if (tid < 96)  cp16(s_gq + (tid - 64) * 4, gw_Q + (tid - 64) * 4);
    else if (tid < 104) cp16(s_disc + (tid - 96) * 4, disc + i0 + (tid - 96) * 4);
    asm volatile("cp.async.commit_group;\n" ::: "memory");

    // ---- fp32 -> fp16 conversions into fragment-strided tiles ----
    for (int j = tid; j < 2048; j += 512) {                // w1
        const float2 v = ((const float2*)w1)[j];
        *(__half2*)(s_w1h + (j >> 4) * W1HS + 2 * (j & 15)) =
            __floats2half2_rn(v.x, v.y);
    }
    {
        const int j = tid;                                 // ie (512 f2)
        const float2 v = ((const float2*)(item_emb + (size_t)i0 * EMB))[j];
        *(__half2*)(s_ieh + (j >> 4) * IEHS + 2 * (j & 15)) =
            __floats2half2_rn(v.x, v.y);
    }

    const float bpv = bp[0];

    // ---- g2 degree-6 Newton interpolation setup (warp 0) ----
    if (wid == 0) {
        const float w2v = w2[0];
        const float b2v = b2[0];
        const float h = 1.0f / 6.0f;
        float fk = sigmoidf(fmaf(w2v, h * (float)(lane < 7 ? lane : 0), b2v));
        const float f0 = __shfl_sync(0xffffffffu, fk, 0);
        const float f1 = __shfl_sync(0xffffffffu, fk, 1);
        const float f2 = __shfl_sync(0xffffffffu, fk, 2);
        const float f3 = __shfl_sync(0xffffffffu, fk, 3);
        const float f4 = __shfl_sync(0xffffffffu, fk, 4);
        const float f5 = __shfl_sync(0xffffffffu, fk, 5);
        const float f6 = __shfl_sync(0xffffffffu, fk, 6);
        if (lane == 0) {
            const float d1 = f1 - f0;
            const float d2 = f2 - 2.0f * f1 + f0;
            const float d3 = f3 - 3.0f * f2 + 3.0f * f1 - f0;
            const float d4 = f4 - 4.0f * f3 + 6.0f * f2 - 4.0f * f1 + f0;
            const float d5 = f5 - 5.0f * f4 + 10.0f * f3 - 10.0f * f2
                             + 5.0f * f1 - f0;
            const float d6 = f6 - 6.0f * f5 + 15.0f * f4 - 20.0f * f3
                             + 15.0f * f2 - 6.0f * f1 + f0;
            s_poly[0] = f0;
            s_poly[1] = d1;
            s_poly[2] = d2 * 0.5f;
            s_poly[3] = d3 * (1.0f / 6.0f);
            s_poly[4] = d4 * (1.0f / 24.0f);
            s_poly[5] = d5 * (1.0f / 120.0f);
            s_poly[6] = d6 * (1.0f / 720.0f);
        }
    }

    asm volatile("cp.async.wait_group 0;\n" ::: "memory");
    __syncthreads();

    // ---- phase B: itemC GEMM on tensor cores + qw' + per-item partials ----
    {
        const int c = 8 * wid + 2 * tig;

        float2 qv[4];
#pragma unroll
        for (int s = 0; s < 4; s++) {
            const int item = 8 * s + gid;
            qv[s] = *(const float2*)(Q + (size_t)(i0 + item) * CONC + c);
        }

        float acc[2][4];
#pragma unroll
        for (int mi = 0; mi < 2; mi++)
#pragma unroll
            for (int r = 0; r < 4; r++) acc[mi][r] = 0.0f;

#pragma unroll
        for (int kc = 0; kc < 2; kc++) {
            uint2 bb;
            bb.x = *(const uint32_t*)(s_w1h + (8 * wid + gid) * W1HS + 16 * kc + 2 * tig);
            bb.y = *(const uint32_t*)(s_w1h + (8 * wid + gid) * W1HS + 16 * kc + 2 * tig + 8);
#pragma unroll
            for (int mi = 0; mi < 2; mi++) {
                uint4 aa;
                aa.x = *(const uint32_t*)(s_ieh + (16 * mi + gid) * IEHS + 16 * kc + 2 * tig);
                aa.y = *(const uint32_t*)(s_ieh + (16 * mi + gid + 8) * IEHS + 16 * kc + 2 * tig);
                aa.z = *(const uint32_t*)(s_ieh + (16 * mi + gid) * IEHS + 16 * kc + 2 * tig + 8);
                aa.w = *(const uint32_t*)(s_ieh + (16 * mi + gid + 8) * IEHS + 16 * kc + 2 * tig + 8);
                mma_f16(acc[mi], aa, bb);
            }
        }

        const float b1c0 = s_b1[c],  b1c1 = s_b1[c + 1];
        const float wp0  = s_wp[c],  wp1  = s_wp[c + 1];
        const float gq0  = s_gq[c],  gq1  = s_gq[c + 1];
        const int   slot = 16 * (wid >> 1) + 4 * tig + 2 * (wid & 1);

        float pr[4], qa[4];
#pragma unroll
        for (int mi = 0; mi < 2; mi++)
#pragma unroll
            for (int h = 0; h < 2; h++) {
                const int s    = 2 * mi + h;
                const int item = 16 * mi + 8 * h + gid;
                const float ic0 = sigt(acc[mi][2 * h]     + b1c0);
                const float ic1 = sigt(acc[mi][2 * h + 1] + b1c1);
                const float q0 = (h == 0) ? ((mi == 0) ? qv[0].x : qv[2].x)
                                          : ((mi == 0) ? qv[1].x : qv[3].x);
                const float q1 = (h == 0) ? ((mi == 0) ? qv[0].y : qv[2].y)
                                          : ((mi == 0) ? qv[1].y : qv[3].y);
                const float qw0 = q0 * wp0;
                const float qw1 = q1 * wp1;
                *(__half2*)(s_qwh + item * QWHS + slot) = __floats2half2_rn(qw0, qw1);
                pr[s] = fmaf(qw0, ic0, qw1 * ic1);
                qa[s] = fmaf(q0, gq0, q1 * gq1);
            }
#pragma unroll
        for (int s = 0; s < 4; s++) {
            pr[s] += __shfl_down_sync(0xffffffffu, pr[s], 2, 4);
            pr[s] += __shfl_down_sync(0xffffffffu, pr[s], 1, 4);
            qa[s] += __shfl_down_sync(0xffffffffu, qa[s], 2, 4);
            qa[s] += __shfl_down_sync(0xffffffffu, qa[s], 1, 4);
        }
        if (tig == 0) {
#pragma unroll
            for (int mi = 0; mi < 2; mi++)
#pragma unroll
                for (int h = 0; h < 2; h++) {
                    const int item = 16 * mi + 8 * h + gid;
                    s_part [wid * 32 + item] = pr[2 * mi + h];
                    s_partq[wid * 32 + item] = qa[2 * mi + h];
                }
        }
    }

    // ---- stu_kernel results become visible ----
    asm volatile("griddepcontrol.wait;" ::: "memory");
    __syncthreads();    // publishes s_part/s_partq/s_qwh

    // cross-warp reduce of per-item partials (warp 0)
    if (tid < 32) {
        float t2 = 0.0f, qa = 0.0f;
#pragma unroll
        for (int w = 0; w < 16; w++) {
            t2 += s_part [w * 32 + tid];
            qa += s_partq[w * 32 + tid];
        }
        s_zc[tid] = fmaf(-s_disc[tid], t2, bpv);
        s_qa[tid] = qa;
    }
    __syncthreads();

    // ---- phase C: term1 GEMM; A fragments straight from gmem (L2-hot) ----
    const int wm = wid >> 1;      // rows 16*wm..+16
    const int wn = wid & 1;       // cols 16*wn..+16

    float acc[2][4];
#pragma unroll
    for (int ni = 0; ni < 2; ni++)
#pragma unroll
        for (int r = 0; r < 4; r++) acc[ni][r] = 0.0f;

    const __half* pa  = g_stuC + wm * 2048 + (gid * 4 + tig) * 8;
    const __half* pb0 = s_qwh + (16 * wn + gid) * QWHS + 4 * tig;
#pragma unroll
    for (int kb = 0; kb < 8; kb++) {
        const uint4 a   = *(const uint4*)(pa + kb * 256);
        const uint2 b0  = *(const uint2*)(pb0 + kb * 16);
        const uint2 b1v = *(const uint2*)(pb0 + 8 * QWHS + kb * 16);
        mma_f16(acc[0], a, b0);
        mma_f16(acc[1], a, b1v);
    }

    // ---- fused epilogue ----
    const float F0 = s_poly[0], D1 = s_poly[1], D2 = s_poly[2],
                D3 = s_poly[3], D4 = s_poly[4], D5 = s_poly[5],
                D6 = s_poly[6];
#pragma unroll
    for (int h = 0; h < 2; h++) {
        const int row = 16 * wm + 8 * h + gid;
        const float gs = g_gsu[row];
        float* orow = out + (size_t)row * ITEMS + i0;
#pragma unroll
        for (int ni = 0; ni < 2; ni++) {
            const int col = 16 * wn + 8 * ni + 2 * tig;
            float res[2];
#pragma unroll
            for (int e = 0; e < 2; e++) {
                const int il = col + e;
                const float t1 = acc[ni][2 * h + e];
                const float z  = fmaf(s_disc[il], t1, s_zc[il]);
                const float P  = sigt(z);
                const float g1 = sigt(gs + s_qa[il]);
                const float v = 6.0f * g1;
                float tp = D6;
                tp = fmaf(v - 5.0f, tp, D5);
                tp = fmaf(v - 4.0f, tp, D4);
                tp = fmaf(v - 3.0f, tp, D3);
                tp = fmaf(v - 2.0f, tp, D2);
                tp = fmaf(v - 1.0f, tp, D1);
                const float g2 = fmaf(v, tp, F0);
                res[e] = fmaf(1.0f - g2, P, g2);
            }
            *(float2*)(orow + col) = make_float2(res[0], res[1]);
        }
    }
}

// ---------------------------------------------------------------------------
extern "C" void kernel_launch(void* const* d_in, const int* in_sizes, int n_in,
                              void* d_out, int out_size) {
    const int*   stu_list = (const int*)  d_in[0];
    const float* stu_emb  = (const float*)d_in[1];
    const float* item_emb = (const float*)d_in[2];
    const float* disc     = (const float*)d_in[3];
    const float* Q        = (const float*)d_in[4];
    const float* w1       = (const float*)d_in[5];
    const float* b1       = (const float*)d_in[6];
    const float* wp       = (const float*)d_in[7];
    const float* bp       = (const float*)d_in[8];
    const float* gw_stu   = (const float*)d_in[9];
    const float* gw_Q     = (const float*)d_in[10];
    const float* w2       = (const float*)d_in[11];
    const float* b2       = (const float*)d_in[12];
    float* out = (float*)d_out;

    stu_kernel<<<16, 512>>>(stu_list, stu_emb, w1, b1, gw_stu);

    cudaFuncSetAttribute(main_kernel, cudaFuncAttributeMaxDynamicSharedMemorySize,
                         SMEM_BYTES);
    cudaLaunchConfig_t cfg = {};
    cfg.gridDim  = dim3(NBLK);
    cfg.blockDim = dim3(512);
    cfg.dynamicSmemBytes = SMEM_BYTES;
    cfg.stream = 0;
    cudaLaunchAttribute attrs[1];
    attrs[0].id = cudaLaunchAttributeProgrammaticStreamSerialization;
    attrs[0].val.programmaticStreamSerializationAllowed = 1;
    cfg.attrs = attrs;
    cfg.numAttrs = 1;
    cudaLaunchKernelEx(&cfg, main_kernel, item_emb, disc, Q, w1, b1, wp, bp,
                       gw_Q, w2, b2, out);
}